// round 2
// baseline (speedup 1.0000x reference)
#include <cuda_runtime.h>
#include <stdint.h>

#define THREADS   256
#define GRID      2368
#define WARPS_PB  (THREADS / 32)
#define NSLICES   (GRID * WARPS_PB)          /* 18944 warp slices */
#define SLICE_CAP 1024u
#define CUTBITS   0x40000000u                /* bit pattern of 2.0f */

__device__ unsigned           g_hist1[1024];       // coarse bins [1024, 2048)
__device__ unsigned           g_histlo[2048];      // fallback full coarse hist
__device__ unsigned           g_hist2[1u << 20];   // fine hist (low 20 bits)
__device__ unsigned           g_part[1024];        // chunk partial sums for fine hist
__device__ unsigned           g_cand[(size_t)NSLICES * SLICE_CAP]; // candidate bit patterns
__device__ unsigned           g_wcnt[NSLICES];     // per-warp-slice counts
__device__ unsigned long long g_zeros;
__device__ unsigned long long g_below;
__device__ int                g_need;              // th below 2.0 -> full fallback
__device__ int                g_ovf;               // candidate slice overflow
__device__ long long          g_idx;
__device__ int                g_bin;               // target coarse bin
__device__ long long          g_rank;              // rank within coarse bin
__device__ float              g_th;
__device__ float              g_step;

__global__ void initk() {
    unsigned t = blockIdx.x * blockDim.x + threadIdx.x;
    unsigned T = gridDim.x * blockDim.x;
    for (unsigned i = t; i < (1u << 20); i += T) g_hist2[i] = 0u;
    for (unsigned i = t; i < 2048u; i += T) g_histlo[i] = 0u;
    for (unsigned i = t; i < 1024u; i += T) g_hist1[i] = 0u;
    if (t == 0) { g_zeros = 0ull; g_below = 0ull; g_need = 0; g_ovf = 0; }
}

// ---------------- Pass 1: coarse hist (|x|>=2.0) + below/zero counts + candidate compaction
__device__ __forceinline__ void p1_elem(unsigned raw, bool act, unsigned* hh,
                                        unsigned& below, unsigned& zeros,
                                        unsigned& pos, int& ovf,
                                        unsigned* __restrict__ slice, int lane) {
    unsigned u = raw & 0x7fffffffu;
    bool cand = act && (u >= CUTBITS);
    if (act && !cand) { below += 1u; if (u == 0u) zeros += 1u; }
    if (cand) atomicAdd(&hh[(u >> 20) - 1024u], 1u);
    unsigned bal = __ballot_sync(0xffffffffu, cand);
    unsigned cnt = __popc(bal);
    if (cnt) {
        if (pos + cnt <= SLICE_CAP) {
            if (cand) slice[pos + __popc(bal & ((1u << lane) - 1u))] = u;
        } else {
            ovf = 1;
        }
        pos += cnt;
    }
}

__global__ void __launch_bounds__(THREADS) pass1(const uint4* __restrict__ x4,
                                                 int n4, int n) {
    __shared__ unsigned sh[4][1024];
    int tid = threadIdx.x;
    for (int i = tid; i < 4096; i += THREADS) ((unsigned*)sh)[i] = 0u;
    __syncthreads();
    unsigned* hh = sh[tid >> 6];

    int lane = tid & 31;
    int warp = tid >> 5;
    int gw = blockIdx.x * WARPS_PB + warp;
    unsigned* slice = g_cand + (size_t)gw * SLICE_CAP;

    unsigned below = 0u, zeros = 0u, pos = 0u;
    int ovf = 0;
    int stride = GRID * THREADS;

    for (int base = blockIdx.x * THREADS + warp * 32; base < n4; base += stride) {
        int i = base + lane;
        bool act = (i < n4);
        uint4 v = act ? x4[i] : make_uint4(0u, 0u, 0u, 0u);
        p1_elem(v.x, act, hh, below, zeros, pos, ovf, slice, lane);
        p1_elem(v.y, act, hh, below, zeros, pos, ovf, slice, lane);
        p1_elem(v.z, act, hh, below, zeros, pos, ovf, slice, lane);
        p1_elem(v.w, act, hh, below, zeros, pos, ovf, slice, lane);
    }
    // tail (n % 4) handled by warp 0 of block 0
    if (blockIdx.x == 0 && warp == 0) {
        int i = (n4 << 2) + lane;
        bool act = (i < n);
        unsigned raw = act ? ((const unsigned*)x4)[i] : 0u;
        p1_elem(raw, act, hh, below, zeros, pos, ovf, slice, lane);
    }

    if (lane == 0) g_wcnt[gw] = (pos < SLICE_CAP) ? pos : SLICE_CAP;
    if (ovf && lane == 0) g_ovf = 1;

    // warp reduce counters, one atomic per warp
    for (int o = 16; o; o >>= 1) {
        below += __shfl_down_sync(0xffffffffu, below, o);
        zeros += __shfl_down_sync(0xffffffffu, zeros, o);
    }
    if (lane == 0) {
        if (below) atomicAdd(&g_below, (unsigned long long)below);
        if (zeros) atomicAdd(&g_zeros, (unsigned long long)zeros);
    }
    __syncthreads();
    for (int b = tid; b < 1024; b += THREADS) {
        unsigned s = sh[0][b] + sh[1][b] + sh[2][b] + sh[3][b];
        if (s) atomicAdd(&g_hist1[b], s);
    }
}

__device__ __forceinline__ unsigned block_scan_1024(unsigned* s, unsigned v, int t) {
    s[t] = v;
    __syncthreads();
    for (int off = 1; off < 1024; off <<= 1) {
        unsigned u = (t >= off) ? s[t - off] : 0u;
        __syncthreads();
        s[t] += u;
        __syncthreads();
    }
    return s[t];
}

// ---------------- Scan 1: compute idx, locate coarse bin (fast path)
__global__ void scan1a(long long n) {
    __shared__ unsigned s[1024];
    int t = threadIdx.x;
    long long zeros = (long long)g_zeros;
    long long below = (long long)g_below;
    long long nnz = n - zeros;
    long long idx = (long long)floorf(0.997f * (float)nnz) + (n - nnz);
    if (idx > n - 1) idx = n - 1;
    if (idx < 0) idx = 0;
    int need = (below > idx) ? 1 : 0;
    if (t == 0) { g_need = need; g_idx = idx; }
    if (need) return;

    unsigned c = g_hist1[t];
    unsigned incl = block_scan_1024(s, c, t);
    long long r = idx - below;
    long long inclL = (long long)incl;
    long long exclL = inclL - (long long)c;
    if (r >= exclL && r < inclL) {
        g_bin = 1024 + t;
        g_rank = r - exclL;
    }
}

// ---------------- Pass 1b (fallback only): full coarse histogram
__global__ void __launch_bounds__(THREADS) pass1b(const uint4* __restrict__ x4,
                                                  int n4, int n) {
    if (!g_need) return;
    __shared__ unsigned sh[4][2048];
    int tid = threadIdx.x;
    for (int i = tid; i < 8192; i += THREADS) ((unsigned*)sh)[i] = 0u;
    __syncthreads();
    unsigned* hh = sh[tid >> 6];
    int stride = gridDim.x * blockDim.x;
#define P1B_PROC(r) atomicAdd(&hh[(r & 0x7fffffffu) >> 20], 1u)
    for (int i = blockIdx.x * blockDim.x + tid; i < n4; i += stride) {
        uint4 v = x4[i];
        P1B_PROC(v.x); P1B_PROC(v.y); P1B_PROC(v.z); P1B_PROC(v.w);
    }
    int rem = n - (n4 << 2);
    if (blockIdx.x == 0 && tid < rem) P1B_PROC(((const unsigned*)x4)[(n4 << 2) + tid]);
#undef P1B_PROC
    __syncthreads();
    for (int b = tid; b < 2048; b += THREADS) {
        unsigned s = sh[0][b] + sh[1][b] + sh[2][b] + sh[3][b];
        if (s) atomicAdd(&g_histlo[b], s);
    }
}

// ---------------- Scan 1b (fallback only): locate coarse bin over full hist
__global__ void scan1b() {
    if (!g_need) return;
    __shared__ unsigned s[1024];
    int t = threadIdx.x;
    unsigned c0 = g_histlo[2 * t];
    unsigned c1 = g_histlo[2 * t + 1];
    unsigned incl = block_scan_1024(s, c0 + c1, t);
    long long r = g_idx;
    long long inclL = (long long)incl;
    long long exclL = inclL - (long long)(c0 + c1);
    if (r >= exclL && r < inclL) {
        if (r < exclL + (long long)c0) { g_bin = 2 * t;     g_rank = r - exclL; }
        else                           { g_bin = 2 * t + 1; g_rank = r - exclL - (long long)c0; }
    }
}

// ---------------- Pass 2 (fast): fine histogram from candidate slices (~12 MB)
__global__ void __launch_bounds__(THREADS) pass2c() {
    if (g_need || g_ovf) return;
    unsigned bin = (unsigned)g_bin;
    int lane = threadIdx.x & 31;
    int gwarp = (blockIdx.x * blockDim.x + threadIdx.x) >> 5;
    int totw = (gridDim.x * blockDim.x) >> 5;
    for (int s = gwarp; s < NSLICES; s += totw) {
        unsigned cnt = g_wcnt[s];
        const unsigned* __restrict__ slice = g_cand + (size_t)s * SLICE_CAP;
        for (unsigned j = lane; j < cnt; j += 32u) {
            unsigned u = slice[j];
            if ((u >> 20) == bin) atomicAdd(&g_hist2[u & 0xFFFFFu], 1u);
        }
    }
}

// ---------------- Pass 2 (fallback): fine histogram from full input
__global__ void __launch_bounds__(THREADS) pass2f(const uint4* __restrict__ x4,
                                                  int n4, int n) {
    if (!(g_need || g_ovf)) return;
    int tid = threadIdx.x;
    unsigned bin = (unsigned)g_bin;
    int stride = gridDim.x * blockDim.x;
#define P2_PROC(r) do { unsigned u = r & 0x7fffffffu; \
        if ((u >> 20) == bin) atomicAdd(&g_hist2[u & 0xFFFFFu], 1u); } while (0)
    for (int i = blockIdx.x * blockDim.x + tid; i < n4; i += stride) {
        uint4 v = x4[i];
        P2_PROC(v.x); P2_PROC(v.y); P2_PROC(v.z); P2_PROC(v.w);
    }
    int rem = n - (n4 << 2);
    if (blockIdx.x == 0 && tid < rem) P2_PROC(((const unsigned*)x4)[(n4 << 2) + tid]);
#undef P2_PROC
}

// ---------------- Scan 2a: per-chunk partial sums of fine hist
__global__ void __launch_bounds__(THREADS) scan2a() {
    __shared__ unsigned red[THREADS / 32];
    int b = blockIdx.x;          // 1024 chunks of 1024 bins
    int tid = threadIdx.x;
    unsigned sum = 0u;
    for (int i = tid; i < 1024; i += THREADS) sum += g_hist2[b * 1024 + i];
    for (int o = 16; o; o >>= 1) sum += __shfl_down_sync(0xffffffffu, sum, o);
    if ((tid & 31) == 0) red[tid >> 5] = sum;
    __syncthreads();
    if (tid == 0) {
        unsigned tot = 0u;
        for (int w = 0; w < THREADS / 32; w++) tot += red[w];
        g_part[b] = tot;
    }
}

// ---------------- Scan 2b: locate exact fine bin -> th, step
__global__ void scan2b() {
    __shared__ unsigned s[1024];
    __shared__ int sc;
    __shared__ long long sr;
    int t = threadIdx.x;
    unsigned c = g_part[t];
    unsigned incl = block_scan_1024(s, c, t);
    long long r = g_rank;
    long long inclL = (long long)incl;
    long long exclL = inclL - (long long)c;
    if (r >= exclL && r < inclL) { sc = t; sr = r - exclL; }
    __syncthreads();
    int chunk = sc;
    long long r2 = sr;
    unsigned c2 = g_hist2[(unsigned)chunk * 1024u + (unsigned)t];
    __syncthreads();
    unsigned incl2 = block_scan_1024(s, c2, t);
    long long incl2L = (long long)incl2;
    long long excl2L = incl2L - (long long)c2;
    if (r2 >= excl2L && r2 < incl2L) {
        unsigned bits = ((unsigned)g_bin << 20) | ((unsigned)chunk * 1024u + (unsigned)t);
        float th = __uint_as_float(bits);
        g_th = th;
        g_step = th / 7.0f;    // n_lv_pos = 2^(4-1)-1 = 7
    }
}

// ---------------- Pass 3: quantize
__device__ __forceinline__ float quant1(float v, float th, float step) {
    if (fabsf(v) <= th) return rintf(v / step) * step;  // IEEE div + RN-even (matches XLA)
    return v;
}

__global__ void __launch_bounds__(THREADS) pass3(const float4* __restrict__ x4,
                                                 float4* __restrict__ o4,
                                                 int n4, int n) {
    int tid = threadIdx.x;
    float th = g_th;
    float step = g_step;
    bool doq = (th > 0.0f);
    int stride = gridDim.x * blockDim.x;
    for (int i = blockIdx.x * blockDim.x + tid; i < n4; i += stride) {
        float4 v = x4[i];
        if (doq) {
            v.x = quant1(v.x, th, step);
            v.y = quant1(v.y, th, step);
            v.z = quant1(v.z, th, step);
            v.w = quant1(v.w, th, step);
        }
        o4[i] = v;
    }
    int rem = n - (n4 << 2);
    if (blockIdx.x == 0 && tid < rem) {
        int i = (n4 << 2) + tid;
        float f = ((const float*)x4)[i];
        ((float*)o4)[i] = doq ? quant1(f, th, step) : f;
    }
}

extern "C" void kernel_launch(void* const* d_in, const int* in_sizes, int n_in,
                              void* d_out, int out_size) {
    const float* x = (const float*)d_in[0];
    int n = in_sizes[0];
    int n4 = n >> 2;

    initk<<<1024, THREADS>>>();
    pass1<<<GRID, THREADS>>>((const uint4*)x, n4, n);
    scan1a<<<1, 1024>>>((long long)n);
    pass1b<<<1184, THREADS>>>((const uint4*)x, n4, n);   // gated (g_need)
    scan1b<<<1, 1024>>>();                               // gated (g_need)
    pass2c<<<296, THREADS>>>();                          // fast path (~12 MB)
    pass2f<<<1184, THREADS>>>((const uint4*)x, n4, n);   // gated (g_need || g_ovf)
    scan2a<<<1024, THREADS>>>();
    scan2b<<<1, 1024>>>();
    pass3<<<GRID, THREADS>>>((const float4*)x, (float4*)d_out, n4, n);
}

// round 3
// speedup vs baseline: 1.1142x; 1.1142x over previous
#include <cuda_runtime.h>
#include <stdint.h>

#define THREADS   256
#define GRID      2368
#define WARPS_PB  (THREADS / 32)
#define WBUF      384u                       /* per-warp staging entries */
#define CAND_CAP  (16u * 1024u * 1024u)      /* 64 MB candidate buffer */
#define CUTBITS   0x40000000u                /* bit pattern of 2.0f */

__device__ unsigned           g_hist1[1024];       // coarse bins [1024, 2048)
__device__ unsigned           g_histlo[2048];      // fallback full coarse hist
__device__ unsigned           g_hist2[1u << 20];   // fine hist (low 20 bits)
__device__ unsigned           g_part[1024];        // chunk partial sums
__device__ unsigned           g_cand[CAND_CAP];    // compacted candidate patterns
__device__ unsigned           g_cur;               // global candidate cursor
__device__ unsigned long long g_zeros;
__device__ int                g_need;              // th below 2.0 -> full fallback
__device__ int                g_ovf;               // candidate buffer overflow
__device__ long long          g_idx;
__device__ int                g_bin;               // target coarse bin
__device__ long long          g_rank;              // rank within coarse bin
__device__ float              g_th;
__device__ float              g_step;

__global__ void initk() {
    unsigned t = blockIdx.x * blockDim.x + threadIdx.x;
    unsigned T = gridDim.x * blockDim.x;
    for (unsigned i = t; i < (1u << 20); i += T) g_hist2[i] = 0u;
    for (unsigned i = t; i < 2048u; i += T) g_histlo[i] = 0u;
    for (unsigned i = t; i < 1024u; i += T) g_hist1[i] = 0u;
    if (t == 0) { g_zeros = 0ull; g_need = 0; g_ovf = 0; g_cur = 0u; }
}

// ---------------- Pass 1: coarse hist (|x|>=2.0) + zero count + staged compaction
__device__ __forceinline__ void warp_flush(unsigned* __restrict__ buf,
                                           unsigned* scnt_w, int lane) {
    unsigned c = *scnt_w;
    unsigned base = 0u;
    if (lane == 0) base = atomicAdd(&g_cur, c);
    base = __shfl_sync(0xffffffffu, base, 0);
    if (base + c <= CAND_CAP) {
        for (unsigned j = lane; j < c; j += 32u) g_cand[base + j] = buf[j];
    } else if (lane == 0) {
        g_ovf = 1;
    }
    __syncwarp();
    if (lane == 0) *scnt_w = 0u;
    __syncwarp();
}

__global__ void __launch_bounds__(THREADS) pass1(const uint4* __restrict__ x4,
                                                 int n4, int n) {
    __shared__ unsigned shist[4][1024];
    __shared__ unsigned sbuf[WARPS_PB][WBUF];
    __shared__ unsigned scnt[WARPS_PB];
    int tid = threadIdx.x, lane = tid & 31, warp = tid >> 5;
    for (int i = tid; i < 4096; i += THREADS) ((unsigned*)shist)[i] = 0u;
    if (tid < WARPS_PB) scnt[tid] = 0u;
    __syncthreads();
    unsigned* hh = shist[warp & 3];
    unsigned* buf = sbuf[warp];
    unsigned* cnt = &scnt[warp];

    unsigned zeros = 0u;

#define P1_PROC(r) do { \
        unsigned u = (r) & 0x7fffffffu; \
        if (act && u >= CUTBITS) { \
            atomicAdd(&hh[(u >> 20) - 1024u], 1u); \
            unsigned p = atomicAdd(cnt, 1u); \
            buf[p] = u; \
        } else if (act) { \
            zeros += (u == 0u) ? 1u : 0u; \
        } \
    } while (0)

    for (int base = blockIdx.x * THREADS + warp * 32; base < n4; base += GRID * THREADS) {
        __syncwarp();
        if (*cnt >= WBUF - 128u) warp_flush(buf, cnt, lane);   // warp-uniform
        int i = base + lane;
        bool act = (i < n4);
        uint4 v = act ? x4[i] : make_uint4(0u, 0u, 0u, 0u);
        P1_PROC(v.x); P1_PROC(v.y); P1_PROC(v.z); P1_PROC(v.w);
    }
    // tail (n % 4): block 0, warp 0
    if (blockIdx.x == 0 && warp == 0) {
        __syncwarp();
        if (*cnt >= WBUF - 32u) warp_flush(buf, cnt, lane);
        int i = (n4 << 2) + lane;
        bool act = (i < n);
        unsigned r = act ? ((const unsigned*)x4)[i] : 0u;
        P1_PROC(r);
    }
#undef P1_PROC
    __syncwarp();
    warp_flush(buf, cnt, lane);   // final drain

    for (int o = 16; o; o >>= 1) zeros += __shfl_down_sync(0xffffffffu, zeros, o);
    if (lane == 0 && zeros) atomicAdd(&g_zeros, (unsigned long long)zeros);
    __syncthreads();
    for (int b = tid; b < 1024; b += THREADS) {
        unsigned s = shist[0][b] + shist[1][b] + shist[2][b] + shist[3][b];
        if (s) atomicAdd(&g_hist1[b], s);
    }
}

// ---------------- shuffle-based inclusive scan over 1024 threads
__device__ unsigned block_scan_1024(unsigned v, int t, unsigned* total) {
    __shared__ unsigned wt[32];
    unsigned s = v;
    for (int o = 1; o < 32; o <<= 1) {
        unsigned u = __shfl_up_sync(0xffffffffu, s, o);
        if ((t & 31) >= o) s += u;
    }
    if ((t & 31) == 31) wt[t >> 5] = s;
    __syncthreads();
    if (t < 32) {
        unsigned w = wt[t];
        for (int o = 1; o < 32; o <<= 1) {
            unsigned u = __shfl_up_sync(0xffffffffu, w, o);
            if (t >= o) w += u;
        }
        wt[t] = w;
    }
    __syncthreads();
    if (t >= 32) s += wt[(t >> 5) - 1];
    *total = wt[31];
    return s;
}

// ---------------- Scan 1: compute idx, locate coarse bin (fast path)
__global__ void scan1a(long long n) {
    int t = threadIdx.x;
    unsigned c = g_hist1[t];
    unsigned tot;
    unsigned incl = block_scan_1024(c, t, &tot);

    long long zeros = (long long)g_zeros;
    long long below = n - (long long)tot;       // elements with |x| < 2.0
    long long nnz = n - zeros;
    long long idx = (long long)floorf(0.997f * (float)nnz) + (n - nnz);
    if (idx > n - 1) idx = n - 1;
    if (idx < 0) idx = 0;
    int need = (below > idx) ? 1 : 0;
    if (t == 0) { g_need = need; g_idx = idx; }
    if (need) return;

    long long r = idx - below;
    long long inclL = (long long)incl;
    long long exclL = inclL - (long long)c;
    if (r >= exclL && r < inclL) {
        g_bin = 1024 + t;
        g_rank = r - exclL;
    }
}

// ---------------- Pass 1b (fallback only): full coarse histogram
__global__ void __launch_bounds__(THREADS) pass1b(const uint4* __restrict__ x4,
                                                  int n4, int n) {
    if (!g_need) return;
    __shared__ unsigned sh[4][2048];
    int tid = threadIdx.x;
    for (int i = tid; i < 8192; i += THREADS) ((unsigned*)sh)[i] = 0u;
    __syncthreads();
    unsigned* hh = sh[tid >> 6];
    int stride = gridDim.x * blockDim.x;
#define P1B_PROC(r) atomicAdd(&hh[((r) & 0x7fffffffu) >> 20], 1u)
    for (int i = blockIdx.x * blockDim.x + tid; i < n4; i += stride) {
        uint4 v = x4[i];
        P1B_PROC(v.x); P1B_PROC(v.y); P1B_PROC(v.z); P1B_PROC(v.w);
    }
    int rem = n - (n4 << 2);
    if (blockIdx.x == 0 && tid < rem) P1B_PROC(((const unsigned*)x4)[(n4 << 2) + tid]);
#undef P1B_PROC
    __syncthreads();
    for (int b = tid; b < 2048; b += THREADS) {
        unsigned s = sh[0][b] + sh[1][b] + sh[2][b] + sh[3][b];
        if (s) atomicAdd(&g_histlo[b], s);
    }
}

// ---------------- Scan 1b (fallback only)
__global__ void scan1b() {
    if (!g_need) return;
    int t = threadIdx.x;
    unsigned c0 = g_histlo[2 * t];
    unsigned c1 = g_histlo[2 * t + 1];
    unsigned tot;
    unsigned incl = block_scan_1024(c0 + c1, t, &tot);
    long long r = g_idx;
    long long inclL = (long long)incl;
    long long exclL = inclL - (long long)(c0 + c1);
    if (r >= exclL && r < inclL) {
        if (r < exclL + (long long)c0) { g_bin = 2 * t;     g_rank = r - exclL; }
        else                           { g_bin = 2 * t + 1; g_rank = r - exclL - (long long)c0; }
    }
}

// ---------------- Pass 2 (fast): fine hist from compacted candidates
__global__ void __launch_bounds__(THREADS) pass2c() {
    if (g_need || g_ovf) return;
    unsigned tot = g_cur;
    unsigned bin = (unsigned)g_bin;
    unsigned stride = gridDim.x * blockDim.x;
    for (unsigned i = blockIdx.x * blockDim.x + threadIdx.x; i < tot; i += stride) {
        unsigned u = g_cand[i];
        if ((u >> 20) == bin) atomicAdd(&g_hist2[u & 0xFFFFFu], 1u);
    }
}

// ---------------- Pass 2 (fallback): fine hist from full input
__global__ void __launch_bounds__(THREADS) pass2f(const uint4* __restrict__ x4,
                                                  int n4, int n) {
    if (!(g_need || g_ovf)) return;
    int tid = threadIdx.x;
    unsigned bin = (unsigned)g_bin;
    int stride = gridDim.x * blockDim.x;
#define P2_PROC(r) do { unsigned u = (r) & 0x7fffffffu; \
        if ((u >> 20) == bin) atomicAdd(&g_hist2[u & 0xFFFFFu], 1u); } while (0)
    for (int i = blockIdx.x * blockDim.x + tid; i < n4; i += stride) {
        uint4 v = x4[i];
        P2_PROC(v.x); P2_PROC(v.y); P2_PROC(v.z); P2_PROC(v.w);
    }
    int rem = n - (n4 << 2);
    if (blockIdx.x == 0 && tid < rem) P2_PROC(((const unsigned*)x4)[(n4 << 2) + tid]);
#undef P2_PROC
}

// ---------------- Scan 2a: per-chunk partial sums of fine hist
__global__ void __launch_bounds__(THREADS) scan2a() {
    __shared__ unsigned red[THREADS / 32];
    int b = blockIdx.x;
    int tid = threadIdx.x;
    unsigned sum = 0u;
    for (int i = tid; i < 1024; i += THREADS) sum += g_hist2[b * 1024 + i];
    for (int o = 16; o; o >>= 1) sum += __shfl_down_sync(0xffffffffu, sum, o);
    if ((tid & 31) == 0) red[tid >> 5] = sum;
    __syncthreads();
    if (tid == 0) {
        unsigned tot = 0u;
        for (int w = 0; w < THREADS / 32; w++) tot += red[w];
        g_part[b] = tot;
    }
}

// ---------------- Scan 2b: locate exact fine bin -> th, step
__global__ void scan2b() {
    __shared__ int sc;
    __shared__ long long sr;
    int t = threadIdx.x;
    unsigned tot;
    unsigned c = g_part[t];
    unsigned incl = block_scan_1024(c, t, &tot);
    long long r = g_rank;
    long long inclL = (long long)incl;
    long long exclL = inclL - (long long)c;
    if (r >= exclL && r < inclL) { sc = t; sr = r - exclL; }
    __syncthreads();
    int chunk = sc;
    long long r2 = sr;
    unsigned c2 = g_hist2[(unsigned)chunk * 1024u + (unsigned)t];
    __syncthreads();
    unsigned incl2 = block_scan_1024(c2, t, &tot);
    long long incl2L = (long long)incl2;
    long long excl2L = incl2L - (long long)c2;
    if (r2 >= excl2L && r2 < incl2L) {
        unsigned bits = ((unsigned)g_bin << 20) | ((unsigned)chunk * 1024u + (unsigned)t);
        float th = __uint_as_float(bits);
        g_th = th;
        g_step = th / 7.0f;   // n_lv_pos = 2^(4-1)-1 = 7
    }
}

// ---------------- Pass 3: quantize
__device__ __forceinline__ float quant1(float v, float th, float step) {
    if (fabsf(v) <= th) return rintf(v / step) * step;  // IEEE div + RN-even (matches XLA)
    return v;
}

__global__ void __launch_bounds__(THREADS) pass3(const float4* __restrict__ x4,
                                                 float4* __restrict__ o4,
                                                 int n4, int n) {
    int tid = threadIdx.x;
    float th = g_th;
    float step = g_step;
    bool doq = (th > 0.0f);
    int stride = gridDim.x * blockDim.x;
    for (int i = blockIdx.x * blockDim.x + tid; i < n4; i += stride) {
        float4 v = x4[i];
        if (doq) {
            v.x = quant1(v.x, th, step);
            v.y = quant1(v.y, th, step);
            v.z = quant1(v.z, th, step);
            v.w = quant1(v.w, th, step);
        }
        o4[i] = v;
    }
    int rem = n - (n4 << 2);
    if (blockIdx.x == 0 && tid < rem) {
        int i = (n4 << 2) + tid;
        float f = ((const float*)x4)[i];
        ((float*)o4)[i] = doq ? quant1(f, th, step) : f;
    }
}

extern "C" void kernel_launch(void* const* d_in, const int* in_sizes, int n_in,
                              void* d_out, int out_size) {
    const float* x = (const float*)d_in[0];
    int n = in_sizes[0];
    int n4 = n >> 2;

    initk<<<1024, THREADS>>>();
    pass1<<<GRID, THREADS>>>((const uint4*)x, n4, n);
    scan1a<<<1, 1024>>>((long long)n);
    pass1b<<<296, THREADS>>>((const uint4*)x, n4, n);    // gated (g_need)
    scan1b<<<1, 1024>>>();                               // gated (g_need)
    pass2c<<<592, THREADS>>>();                          // fast path (~12 MB)
    pass2f<<<296, THREADS>>>((const uint4*)x, n4, n);    // gated (g_need || g_ovf)
    scan2a<<<1024, THREADS>>>();
    scan2b<<<1, 1024>>>();
    pass3<<<GRID, THREADS>>>((const float4*)x, (float4*)d_out, n4, n);
}